// round 16
// baseline (speedup 1.0000x reference)
#include <cuda_runtime.h>
#include <cuda_fp16.h>
#include <math.h>
#include <stdint.h>

#define NN 8192
#define INF_ 512
#define OUTF 256

// ---- scratch (device globals; no allocation allowed) ----
__device__ __half d_gh[(size_t)NN * NN];     // fp16 copy of g (128 MB)
__device__ __half d_featsh[(size_t)NN * INF_];
__device__ __half d_Wh[768 * 512];           // [768,512] transposed packed weights, fp16
__device__ float  d_C1[(size_t)NN * 768];    // row-major [N,768] = [xWl | xWh | relu(xWm)]
__device__ __half d_C1t[(size_t)512 * NN];   // transposed first 512 cols, fp16 (B of gemm2)
__device__ float  d_C2[(size_t)NN * 512];    // g @ C1[:, :512]
__device__ float  d_rinv_x[NN];
__device__ float  d_rinv_g[NN];

// ===========================================================================
// helpers
// ===========================================================================
__device__ __forceinline__ uint32_t smem_u32(const void* p) {
    uint32_t a;
    asm("{ .reg .u64 t; cvta.to.shared.u64 t, %1; cvt.u32.u64 %0, t; }" : "=r"(a) : "l"(p));
    return a;
}
__device__ __forceinline__ void cp_async16(uint32_t dst, const void* src) {
    asm volatile("cp.async.cg.shared.global [%0], [%1], 16;" :: "r"(dst), "l"(src));
}
__device__ __forceinline__ void mma_f16(float* d, const uint32_t* a, const uint32_t* b) {
    asm volatile(
        "mma.sync.aligned.m16n8k16.row.col.f32.f16.f16.f32 "
        "{%0,%1,%2,%3},{%4,%5,%6,%7},{%8,%9},{%0,%1,%2,%3};"
        : "+f"(d[0]), "+f"(d[1]), "+f"(d[2]), "+f"(d[3])
        : "r"(a[0]), "r"(a[1]), "r"(a[2]), "r"(a[3]), "r"(b[0]), "r"(b[1]));
}
// f16-accumulate variants (full-rate HMMA path)
__device__ __forceinline__ void mma_h_init(uint32_t* d, const uint32_t* a, const uint32_t* b,
                                           uint32_t z) {
    asm volatile(
        "mma.sync.aligned.m16n8k16.row.col.f16.f16.f16.f16 "
        "{%0,%1},{%2,%3,%4,%5},{%6,%7},{%8,%8};"
        : "=r"(d[0]), "=r"(d[1])
        : "r"(a[0]), "r"(a[1]), "r"(a[2]), "r"(a[3]), "r"(b[0]), "r"(b[1]), "r"(z));
}
__device__ __forceinline__ void mma_h_acc(uint32_t* d, const uint32_t* a, const uint32_t* b) {
    asm volatile(
        "mma.sync.aligned.m16n8k16.row.col.f16.f16.f16.f16 "
        "{%0,%1},{%2,%3,%4,%5},{%6,%7},{%0,%1};"
        : "+r"(d[0]), "+r"(d[1])
        : "r"(a[0]), "r"(a[1]), "r"(a[2]), "r"(a[3]), "r"(b[0]), "r"(b[1]));
}
__device__ __forceinline__ void ldm_x4(uint32_t addr, uint32_t* r) {
    asm volatile("ldmatrix.sync.aligned.m8n8.x4.shared.b16 {%0,%1,%2,%3}, [%4];"
                 : "=r"(r[0]), "=r"(r[1]), "=r"(r[2]), "=r"(r[3]) : "r"(addr));
}

// ===========================================================================
// fused: blocks [0,1024) do rowsum_feats (+fp16 copy); blocks [1024,2560)
// pack weights transposed + fp16.
// ===========================================================================
__global__ void prep_fused(const float* __restrict__ feats, float* __restrict__ rinv,
                           __half* __restrict__ fh,
                           const float* __restrict__ wl, const float* __restrict__ wh,
                           const float* __restrict__ wm, __half* __restrict__ wt) {
    if (blockIdx.x < 1024) {
        int w = (blockIdx.x * 256 + threadIdx.x) >> 5;
        int lane = threadIdx.x & 31;
        const float4* p = (const float4*)(feats + (size_t)w * INF_);
        __half2* oh = (__half2*)(fh + (size_t)w * INF_);
        float s = 0.f;
        #pragma unroll
        for (int i = lane; i < INF_ / 4; i += 32) {
            float4 v = p[i];
            s += v.x + v.y + v.z + v.w;
            oh[i * 2]     = __floats2half2_rn(v.x, v.y);
            oh[i * 2 + 1] = __floats2half2_rn(v.z, v.w);
        }
        #pragma unroll
        for (int off = 16; off; off >>= 1) s += __shfl_xor_sync(0xffffffffu, s, off);
        if (lane == 0) rinv[w] = (s != 0.f) ? (1.f / s) : 0.f;
    } else {
        int idx = (blockIdx.x - 1024) * 256 + threadIdx.x;
        if (idx < 768 * 512) {
            int n = idx / 512, k = idx % 512;
            float v;
            if (n < 256)       v = wl[k * 256 + n];
            else if (n < 512)  v = wh[k * 256 + (n - 256)];
            else               v = wm[k * 256 + (n - 512)];
            wt[idx] = __float2half_rn(v);
        }
    }
}

// ===========================================================================
// 1/(1+rowsum(g)) + fp16 copy of g. One block per row.
// ===========================================================================
__global__ void rowsum_g(const float* __restrict__ g, float* __restrict__ rinvg,
                         __half* __restrict__ gh) {
    int row = blockIdx.x;
    const float4* p = (const float4*)(g + (size_t)row * NN);
    __half2* oh = (__half2*)(gh + (size_t)row * NN);
    float s = 0.f;
    for (int i = threadIdx.x; i < NN / 4; i += 256) {
        float4 v = p[i];
        s += v.x + v.y + v.z + v.w;
        oh[i * 2]     = __floats2half2_rn(v.x, v.y);
        oh[i * 2 + 1] = __floats2half2_rn(v.z, v.w);
    }
    #pragma unroll
    for (int off = 16; off; off >>= 1) s += __shfl_xor_sync(0xffffffffu, s, off);
    __shared__ float red[8];
    int w = threadIdx.x >> 5, lane = threadIdx.x & 31;
    if (lane == 0) red[w] = s;
    __syncthreads();
    if (threadIdx.x == 0) {
        float t = 1.f;
        #pragma unroll
        for (int i = 0; i < 8; i++) t += red[i];
        rinvg[row] = (t != 0.f) ? (1.f / t) : 0.f;
    }
}

// ===========================================================================
// shared GEMM geometry (proven R12 config): CTA 128x128x32, 128 threads,
// 4 warps of 64x64, 4-stage cp.async, PW=20, two __syncthreads per kt.
// ===========================================================================
#define BM 128
#define BN 128
#define BK 32                            // halves per stage along K
#define PW 20                            // 32-bit words per smem row (16 data + 4 pad)
#define STAGES 4
#define TILE_WORDS (BM * PW)             // 2560
#define STAGE_WORDS (2 * TILE_WORDS)     // 5120
#define GSMEM_BYTES (STAGES * STAGE_WORDS * 4)  // 81920

// ---------------------------------------------------------------------------
// gemm1 (f32 accumulate): C1 = rinv_x * feats @ Wh^T ; relu cols>=512;
// writes fp32 C1 row-major and fp16 transposed C1t for cols<512.
// ---------------------------------------------------------------------------
__global__ void __launch_bounds__(128, 2)
gemm_h(const __half* __restrict__ A, int lda,
       const __half* __restrict__ B, int ldb, int K,
       float* __restrict__ Crm, int ldc,
       __half* __restrict__ Ct,
       const float* __restrict__ rowscale)
{
    extern __shared__ uint32_t sm32[];
    const uint32_t smbase = smem_u32(sm32);

    const int tid = threadIdx.x;
    const int lane = tid & 31, wid = tid >> 5;
    const int wm = (wid & 1) * 64;
    const int wn = (wid >> 1) * 64;
    const int m0 = blockIdx.y * BM;
    const int n0 = blockIdx.x * BN;

    const int lrow = tid >> 2;
    const int lch  = tid & 3;
    const __half* Ag = A + (size_t)(m0 + lrow) * lda + lch * 8;
    const __half* Bg = B + (size_t)(n0 + lrow) * ldb + lch * 8;
    const uint32_t adst = smbase + (uint32_t)((lrow * PW + lch * 4) * 4);
    const uint32_t bdst = adst + TILE_WORDS * 4;

    const int KT = K / BK;

    #pragma unroll
    for (int s = 0; s < STAGES - 1; s++) {
        uint32_t so = (uint32_t)(s * STAGE_WORDS * 4);
        int ko = s * BK;
        #pragma unroll
        for (int rb = 0; rb < 4; rb++) {
            cp_async16(adst + so + rb * 32 * PW * 4, Ag + (size_t)(rb * 32) * lda + ko);
            cp_async16(bdst + so + rb * 32 * PW * 4, Bg + (size_t)(rb * 32) * ldb + ko);
        }
        asm volatile("cp.async.commit_group;" ::: "memory");
    }

    float acc[4][8][4];
    #pragma unroll
    for (int i = 0; i < 4; i++)
        #pragma unroll
        for (int j = 0; j < 8; j++)
            #pragma unroll
            for (int q = 0; q < 4; q++) acc[i][j][q] = 0.f;

    const uint32_t aoff = (uint32_t)((lane & 15) * PW * 4 + (lane >> 4) * 16);
    const uint32_t boff = (uint32_t)(((lane & 7) + ((lane & 16) ? 8 : 0)) * PW * 4 +
                                     ((lane & 8) ? 16 : 0));
    const int fr = lane >> 2;
    const int c2 = (lane & 3) * 2;

    for (int kt = 0; kt < KT; kt++) {
        asm volatile("cp.async.wait_group 2;" ::: "memory");
        __syncthreads();

        const int ps = kt + STAGES - 1;
        if (ps < KT) {
            uint32_t so = (uint32_t)((ps & (STAGES - 1)) * STAGE_WORDS * 4);
            int ko = ps * BK;
            #pragma unroll
            for (int rb = 0; rb < 4; rb++) {
                cp_async16(adst + so + rb * 32 * PW * 4, Ag + (size_t)(rb * 32) * lda + ko);
                cp_async16(bdst + so + rb * 32 * PW * 4, Bg + (size_t)(rb * 32) * ldb + ko);
            }
        }
        asm volatile("cp.async.commit_group;" ::: "memory");

        const uint32_t sA = smbase + (uint32_t)((kt & (STAGES - 1)) * STAGE_WORDS * 4);
        const uint32_t sB = sA + TILE_WORDS * 4;

        #pragma unroll
        for (int kk = 0; kk < 2; kk++) {
            const uint32_t kb = (uint32_t)(kk * 32);
            uint32_t af[4][4];
            #pragma unroll
            for (int i = 0; i < 4; i++)
                ldm_x4(sA + (uint32_t)((wm + i * 16) * PW * 4) + kb + aoff, af[i]);
            uint32_t bfr[4][4];
            #pragma unroll
            for (int jp = 0; jp < 4; jp++)
                ldm_x4(sB + (uint32_t)((wn + jp * 16) * PW * 4) + kb + boff, bfr[jp]);
            #pragma unroll
            for (int i = 0; i < 4; i++)
                #pragma unroll
                for (int j = 0; j < 8; j++)
                    mma_f16(acc[i][j], af[i], &bfr[j >> 1][(j & 1) * 2]);
        }
        __syncthreads();
    }

    const bool dorelu = (n0 >= 512);
    const bool dotr   = (n0 < 512);
    #pragma unroll
    for (int i = 0; i < 4; i++) {
        const int row0 = m0 + wm + i * 16 + fr;
        const int row1 = row0 + 8;
        const float s0 = rowscale[row0];
        const float s1 = rowscale[row1];
        #pragma unroll
        for (int j = 0; j < 8; j++) {
            const int col = n0 + wn + j * 8 + c2;
            float v0 = acc[i][j][0] * s0, v1 = acc[i][j][1] * s0;
            float v2 = acc[i][j][2] * s1, v3 = acc[i][j][3] * s1;
            if (dorelu) {
                v0 = fmaxf(v0, 0.f); v1 = fmaxf(v1, 0.f);
                v2 = fmaxf(v2, 0.f); v3 = fmaxf(v3, 0.f);
            }
            *(float2*)&Crm[(size_t)row0 * ldc + col] = make_float2(v0, v1);
            *(float2*)&Crm[(size_t)row1 * ldc + col] = make_float2(v2, v3);
            if (dotr) {
                Ct[(size_t)col * NN + row0] = __float2half_rn(v0);
                Ct[(size_t)(col + 1) * NN + row0] = __float2half_rn(v1);
                Ct[(size_t)col * NN + row1] = __float2half_rn(v2);
                Ct[(size_t)(col + 1) * NN + row1] = __float2half_rn(v3);
            }
        }
    }
}

// ---------------------------------------------------------------------------
// gemm2 (f16 accumulate per kt, promote to f32 each kt): C2 = gh @ C1t^T
// ---------------------------------------------------------------------------
__global__ void __launch_bounds__(128, 2)
gemm2_h(const __half* __restrict__ A, int lda,
        const __half* __restrict__ B, int ldb, int K,
        float* __restrict__ Crm, int ldc)
{
    extern __shared__ uint32_t sm32[];
    const uint32_t smbase = smem_u32(sm32);

    const int tid = threadIdx.x;
    const int lane = tid & 31, wid = tid >> 5;
    const int wm = (wid & 1) * 64;
    const int wn = (wid >> 1) * 64;
    const int m0 = blockIdx.y * BM;
    const int n0 = blockIdx.x * BN;

    const int lrow = tid >> 2;
    const int lch  = tid & 3;
    const __half* Ag = A + (size_t)(m0 + lrow) * lda + lch * 8;
    const __half* Bg = B + (size_t)(n0 + lrow) * ldb + lch * 8;
    const uint32_t adst = smbase + (uint32_t)((lrow * PW + lch * 4) * 4);
    const uint32_t bdst = adst + TILE_WORDS * 4;

    const int KT = K / BK;

    #pragma unroll
    for (int s = 0; s < STAGES - 1; s++) {
        uint32_t so = (uint32_t)(s * STAGE_WORDS * 4);
        int ko = s * BK;
        #pragma unroll
        for (int rb = 0; rb < 4; rb++) {
            cp_async16(adst + so + rb * 32 * PW * 4, Ag + (size_t)(rb * 32) * lda + ko);
            cp_async16(bdst + so + rb * 32 * PW * 4, Bg + (size_t)(rb * 32) * ldb + ko);
        }
        asm volatile("cp.async.commit_group;" ::: "memory");
    }

    float accf[4][8][4];
    #pragma unroll
    for (int i = 0; i < 4; i++)
        #pragma unroll
        for (int j = 0; j < 8; j++)
            #pragma unroll
            for (int q = 0; q < 4; q++) accf[i][j][q] = 0.f;

    const uint32_t aoff = (uint32_t)((lane & 15) * PW * 4 + (lane >> 4) * 16);
    const uint32_t boff = (uint32_t)(((lane & 7) + ((lane & 16) ? 8 : 0)) * PW * 4 +
                                     ((lane & 8) ? 16 : 0));
    const int fr = lane >> 2;
    const int c2 = (lane & 3) * 2;

    for (int kt = 0; kt < KT; kt++) {
        asm volatile("cp.async.wait_group 2;" ::: "memory");
        __syncthreads();

        const int ps = kt + STAGES - 1;
        if (ps < KT) {
            uint32_t so = (uint32_t)((ps & (STAGES - 1)) * STAGE_WORDS * 4);
            int ko = ps * BK;
            #pragma unroll
            for (int rb = 0; rb < 4; rb++) {
                cp_async16(adst + so + rb * 32 * PW * 4, Ag + (size_t)(rb * 32) * lda + ko);
                cp_async16(bdst + so + rb * 32 * PW * 4, Bg + (size_t)(rb * 32) * ldb + ko);
            }
        }
        asm volatile("cp.async.commit_group;" ::: "memory");

        const uint32_t sA = smbase + (uint32_t)((kt & (STAGES - 1)) * STAGE_WORDS * 4);
        const uint32_t sB = sA + TILE_WORDS * 4;

        uint32_t acc16[4][8][2];
        const uint32_t z = 0;

        // kk = 0: fresh f16 accumulators (C = 0)
        {
            uint32_t af[4][4];
            #pragma unroll
            for (int i = 0; i < 4; i++)
                ldm_x4(sA + (uint32_t)((wm + i * 16) * PW * 4) + aoff, af[i]);
            uint32_t bfr[4][4];
            #pragma unroll
            for (int jp = 0; jp < 4; jp++)
                ldm_x4(sB + (uint32_t)((wn + jp * 16) * PW * 4) + boff, bfr[jp]);
            #pragma unroll
            for (int i = 0; i < 4; i++)
                #pragma unroll
                for (int j = 0; j < 8; j++)
                    mma_h_init(acc16[i][j], af[i], &bfr[j >> 1][(j & 1) * 2], z);
        }
        // kk = 1: accumulate in f16
        {
            uint32_t af[4][4];
            #pragma unroll
            for (int i = 0; i < 4; i++)
                ldm_x4(sA + (uint32_t)((wm + i * 16) * PW * 4) + 32 + aoff, af[i]);
            uint32_t bfr[4][4];
            #pragma unroll
            for (int jp = 0; jp < 4; jp++)
                ldm_x4(sB + (uint32_t)((wn + jp * 16) * PW * 4) + 32 + boff, bfr[jp]);
            #pragma unroll
            for (int i = 0; i < 4; i++)
                #pragma unroll
                for (int j = 0; j < 8; j++)
                    mma_h_acc(acc16[i][j], af[i], &bfr[j >> 1][(j & 1) * 2]);
        }
        __syncthreads();

        // promote: f16 chunk sums -> f32 accumulators
        #pragma unroll
        for (int i = 0; i < 4; i++)
            #pragma unroll
            for (int j = 0; j < 8; j++) {
                float2 lo = __half22float2(*(__half2*)&acc16[i][j][0]);
                float2 hi = __half22float2(*(__half2*)&acc16[i][j][1]);
                accf[i][j][0] += lo.x; accf[i][j][1] += lo.y;
                accf[i][j][2] += hi.x; accf[i][j][3] += hi.y;
            }
    }

    #pragma unroll
    for (int i = 0; i < 4; i++) {
        const int row0 = m0 + wm + i * 16 + fr;
        const int row1 = row0 + 8;
        #pragma unroll
        for (int j = 0; j < 8; j++) {
            const int col = n0 + wn + j * 8 + c2;
            *(float2*)&Crm[(size_t)row0 * ldc + col] = make_float2(accf[i][j][0], accf[i][j][1]);
            *(float2*)&Crm[(size_t)row1 * ldc + col] = make_float2(accf[i][j][2], accf[i][j][3]);
        }
    }
}

// ===========================================================================
// finalize: per-row attention epilogue
// ===========================================================================
__global__ void finalize(const float* __restrict__ C1, const float* __restrict__ C2,
                         const float* __restrict__ rinvg,
                         const float* __restrict__ al, const float* __restrict__ ah,
                         const float* __restrict__ amv,
                         const float* __restrict__ attv, float* __restrict__ out)
{
    int i = blockIdx.x;
    int c = threadIdx.x;
    const float* c1 = C1 + (size_t)i * 768;
    const float* c2 = C2 + (size_t)i * 512;
    float inv = rinvg[i];

    float xl = c1[c], xh = c1[256 + c], om = c1[512 + c];
    float gl = c2[c], gh = c2[256 + c];

    float ol = fmaxf((xl + gl) * inv, 0.f);
    float oh = fmaxf(xh - (xh + gh) * inv, 0.f);

    float v0 = ol * al[c], v1 = oh * ah[c], v2 = om * amv[c];
    #pragma unroll
    for (int off = 16; off; off >>= 1) {
        v0 += __shfl_xor_sync(0xffffffffu, v0, off);
        v1 += __shfl_xor_sync(0xffffffffu, v1, off);
        v2 += __shfl_xor_sync(0xffffffffu, v2, off);
    }
    __shared__ float r0[8], r1[8], r2[8];
    __shared__ float att[3];
    int w = c >> 5, lane = c & 31;
    if (lane == 0) { r0[w] = v0; r1[w] = v1; r2[w] = v2; }
    __syncthreads();
    if (c == 0) {
        float t0 = 0.f, t1 = 0.f, t2 = 0.f;
        #pragma unroll
        for (int k = 0; k < 8; k++) { t0 += r0[k]; t1 += r1[k]; t2 += r2[k]; }
        float s0 = 1.f / (1.f + expf(-t0));
        float s1 = 1.f / (1.f + expf(-t1));
        float s2 = 1.f / (1.f + expf(-t2));
        float l[3];
        #pragma unroll
        for (int j = 0; j < 3; j++)
            l[j] = (s0 * attv[0 * 3 + j] + s1 * attv[1 * 3 + j] + s2 * attv[2 * 3 + j]) * (1.f / 3.f);
        float mx = fmaxf(l[0], fmaxf(l[1], l[2]));
        float e0 = expf(l[0] - mx), e1 = expf(l[1] - mx), e2 = expf(l[2] - mx);
        float esum = e0 + e1 + e2;
        att[0] = e0 / esum; att[1] = e1 / esum; att[2] = e2 / esum;
    }
    __syncthreads();
    out[(size_t)i * 256 + c] = 3.f * (att[0] * ol + att[1] * oh + att[2] * om);
}

// ===========================================================================
extern "C" void kernel_launch(void* const* d_in, const int* in_sizes, int n_in,
                              void* d_out, int out_size)
{
    const float* g     = (const float*)d_in[0];
    const float* feats = (const float*)d_in[1];
    const float* wl    = (const float*)d_in[3];
    const float* wh    = (const float*)d_in[4];
    const float* wm    = (const float*)d_in[5];
    const float* al    = (const float*)d_in[6];
    const float* ah    = (const float*)d_in[7];
    const float* amv   = (const float*)d_in[8];
    const float* attv  = (const float*)d_in[9];
    float* out = (float*)d_out;

    float *C1, *C2, *rx, *rg;
    __half *GH, *FH, *WH, *C1t;
    cudaGetSymbolAddress((void**)&GH, d_gh);
    cudaGetSymbolAddress((void**)&FH, d_featsh);
    cudaGetSymbolAddress((void**)&WH, d_Wh);
    cudaGetSymbolAddress((void**)&C1, d_C1);
    cudaGetSymbolAddress((void**)&C1t, d_C1t);
    cudaGetSymbolAddress((void**)&C2, d_C2);
    cudaGetSymbolAddress((void**)&rx, d_rinv_x);
    cudaGetSymbolAddress((void**)&rg, d_rinv_g);

    cudaFuncSetAttribute(gemm_h, cudaFuncAttributeMaxDynamicSharedMemorySize, GSMEM_BYTES);
    cudaFuncSetAttribute(gemm2_h, cudaFuncAttributeMaxDynamicSharedMemorySize, GSMEM_BYTES);

    // launch 0: fused rowsum_feats + pack_w
    prep_fused<<<1024 + 1536, 256>>>(feats, rx, FH, wl, wh, wm, WH);
    // launch 1: rowsum_g + fp16 copy of g
    rowsum_g<<<NN, 256>>>(g, rg, GH);
    // launch 2: gemm1 (f32 acc): C1 = rinv_x * feats @ Wh^T (+relu mlp, +fp16 C1t)
    gemm_h<<<dim3(6, 64), 128, GSMEM_BYTES>>>(FH, INF_, WH, INF_, INF_,
                                              C1, 768, C1t, rx);
    // launch 3 (profiled slot): gemm2 (f16 acc + promote): C2 = gh @ C1t^T
    gemm2_h<<<dim3(4, 64), 128, GSMEM_BYTES>>>(GH, NN, C1t, NN, NN, C2, 512);
    // launch 4: attention epilogue
    finalize<<<NN, 256>>>(C1, C2, rg, al, ah, amv, attv, out);
}

// round 17
// speedup vs baseline: 1.2956x; 1.2956x over previous
#include <cuda_runtime.h>
#include <cuda_fp16.h>
#include <math.h>
#include <stdint.h>

#define NN 8192
#define INF_ 512
#define OUTF 256

// ---- scratch (device globals; no allocation allowed) ----
__device__ __half d_gh[(size_t)NN * NN];     // fp16 copy of g (128 MB)
__device__ __half d_featsh[(size_t)NN * INF_];
__device__ __half d_Wh[768 * 512];           // [768,512] transposed packed weights, fp16
__device__ float  d_C1[(size_t)NN * 768];    // row-major [N,768] = [xWl | xWh | relu(xWm)]
__device__ __half d_C1t[(size_t)512 * NN];   // transposed first 512 cols, fp16 (B of gemm2)
__device__ float  d_C2[(size_t)NN * 512];    // g @ C1[:, :512]
__device__ float  d_rinv_x[NN];
__device__ float  d_rinv_g[NN];

// ===========================================================================
// helpers
// ===========================================================================
__device__ __forceinline__ uint32_t smem_u32(const void* p) {
    uint32_t a;
    asm("{ .reg .u64 t; cvta.to.shared.u64 t, %1; cvt.u32.u64 %0, t; }" : "=r"(a) : "l"(p));
    return a;
}
__device__ __forceinline__ void cp_async16(uint32_t dst, const void* src) {
    asm volatile("cp.async.cg.shared.global [%0], [%1], 16;" :: "r"(dst), "l"(src));
}
__device__ __forceinline__ void mma_f16(float* d, const uint32_t* a, const uint32_t* b) {
    asm volatile(
        "mma.sync.aligned.m16n8k16.row.col.f32.f16.f16.f32 "
        "{%0,%1,%2,%3},{%4,%5,%6,%7},{%8,%9},{%0,%1,%2,%3};"
        : "+f"(d[0]), "+f"(d[1]), "+f"(d[2]), "+f"(d[3])
        : "r"(a[0]), "r"(a[1]), "r"(a[2]), "r"(a[3]), "r"(b[0]), "r"(b[1]));
}
__device__ __forceinline__ void ldm_x4(uint32_t addr, uint32_t* r) {
    asm volatile("ldmatrix.sync.aligned.m8n8.x4.shared.b16 {%0,%1,%2,%3}, [%4];"
                 : "=r"(r[0]), "=r"(r[1]), "=r"(r[2]), "=r"(r[3]) : "r"(addr));
}

// ===========================================================================
// fused: blocks [0,1024) do rowsum_feats (+fp16 copy); blocks [1024,2560)
// pack weights transposed + fp16.
// ===========================================================================
__global__ void prep_fused(const float* __restrict__ feats, float* __restrict__ rinv,
                           __half* __restrict__ fh,
                           const float* __restrict__ wl, const float* __restrict__ wh,
                           const float* __restrict__ wm, __half* __restrict__ wt) {
    if (blockIdx.x < 1024) {
        int w = (blockIdx.x * 256 + threadIdx.x) >> 5;
        int lane = threadIdx.x & 31;
        const float4* p = (const float4*)(feats + (size_t)w * INF_);
        __half2* oh = (__half2*)(fh + (size_t)w * INF_);
        float s = 0.f;
        #pragma unroll
        for (int i = lane; i < INF_ / 4; i += 32) {
            float4 v = p[i];
            s += v.x + v.y + v.z + v.w;
            oh[i * 2]     = __floats2half2_rn(v.x, v.y);
            oh[i * 2 + 1] = __floats2half2_rn(v.z, v.w);
        }
        #pragma unroll
        for (int off = 16; off; off >>= 1) s += __shfl_xor_sync(0xffffffffu, s, off);
        if (lane == 0) rinv[w] = (s != 0.f) ? (1.f / s) : 0.f;
    } else {
        int idx = (blockIdx.x - 1024) * 256 + threadIdx.x;
        if (idx < 768 * 512) {
            int n = idx / 512, k = idx % 512;
            float v;
            if (n < 256)       v = wl[k * 256 + n];
            else if (n < 512)  v = wh[k * 256 + (n - 256)];
            else               v = wm[k * 256 + (n - 512)];
            wt[idx] = __float2half_rn(v);
        }
    }
}

// ===========================================================================
// 1/(1+rowsum(g)) + fp16 copy of g. One block per row.
// ===========================================================================
__global__ void rowsum_g(const float* __restrict__ g, float* __restrict__ rinvg,
                         __half* __restrict__ gh) {
    int row = blockIdx.x;
    const float4* p = (const float4*)(g + (size_t)row * NN);
    __half2* oh = (__half2*)(gh + (size_t)row * NN);
    float s = 0.f;
    for (int i = threadIdx.x; i < NN / 4; i += 256) {
        float4 v = p[i];
        s += v.x + v.y + v.z + v.w;
        oh[i * 2]     = __floats2half2_rn(v.x, v.y);
        oh[i * 2 + 1] = __floats2half2_rn(v.z, v.w);
    }
    #pragma unroll
    for (int off = 16; off; off >>= 1) s += __shfl_xor_sync(0xffffffffu, s, off);
    __shared__ float red[8];
    int w = threadIdx.x >> 5, lane = threadIdx.x & 31;
    if (lane == 0) red[w] = s;
    __syncthreads();
    if (threadIdx.x == 0) {
        float t = 1.f;
        #pragma unroll
        for (int i = 0; i < 8; i++) t += red[i];
        rinvg[row] = (t != 0.f) ? (1.f / t) : 0.f;
    }
}

// ===========================================================================
// fp16 mma.sync GEMM (f32 accumulate): C[M,N] = A[M,K] @ B[N,K]^T
// CTA 128x128x32, 128 threads: 4 warps of 64x64. 4-stage cp.async pipeline.
// ONE __syncthreads per kt (prefetch at kt targets the slot fully consumed
// at kt-1; the top barrier orders read-before-overwrite). All 16 ldmatrix
// hoisted ahead of the 64 HMMA for maximum overlap window.
// mode 0: scale rows by rowscale, relu if n0>=512; write fp32 Crm and
//         (n<512) fp16 transposed Ct.   mode 1: plain fp32 store.
// ===========================================================================
#define BM 128
#define BN 128
#define BK 32                            // halves per stage along K
#define PW 20                            // 32-bit words per smem row (16 data + 4 pad)
#define STAGES 4
#define TILE_WORDS (BM * PW)             // 2560
#define STAGE_WORDS (2 * TILE_WORDS)     // 5120
#define GSMEM_BYTES (STAGES * STAGE_WORDS * 4)  // 81920

__global__ void __launch_bounds__(128, 2)
gemm_h(const __half* __restrict__ A, int lda,
       const __half* __restrict__ B, int ldb, int K, int mode,
       float* __restrict__ Crm, int ldc,
       __half* __restrict__ Ct,
       const float* __restrict__ rowscale)
{
    extern __shared__ uint32_t sm32[];
    const uint32_t smbase = smem_u32(sm32);

    const int tid = threadIdx.x;
    const int lane = tid & 31, wid = tid >> 5;
    const int wm = (wid & 1) * 64;
    const int wn = (wid >> 1) * 64;
    const int m0 = blockIdx.y * BM;
    const int n0 = blockIdx.x * BN;

    const int lrow = tid >> 2;
    const int lch  = tid & 3;
    const __half* Ag = A + (size_t)(m0 + lrow) * lda + lch * 8;
    const __half* Bg = B + (size_t)(n0 + lrow) * ldb + lch * 8;
    const uint32_t adst = smbase + (uint32_t)((lrow * PW + lch * 4) * 4);
    const uint32_t bdst = adst + TILE_WORDS * 4;

    const int KT = K / BK;

    #pragma unroll
    for (int s = 0; s < STAGES - 1; s++) {
        uint32_t so = (uint32_t)(s * STAGE_WORDS * 4);
        int ko = s * BK;
        #pragma unroll
        for (int rb = 0; rb < 4; rb++) {
            cp_async16(adst + so + rb * 32 * PW * 4, Ag + (size_t)(rb * 32) * lda + ko);
            cp_async16(bdst + so + rb * 32 * PW * 4, Bg + (size_t)(rb * 32) * ldb + ko);
        }
        asm volatile("cp.async.commit_group;" ::: "memory");
    }

    float acc[4][8][4];
    #pragma unroll
    for (int i = 0; i < 4; i++)
        #pragma unroll
        for (int j = 0; j < 8; j++)
            #pragma unroll
            for (int q = 0; q < 4; q++) acc[i][j][q] = 0.f;

    const uint32_t aoff = (uint32_t)((lane & 15) * PW * 4 + (lane >> 4) * 16);
    const uint32_t boff = (uint32_t)(((lane & 7) + ((lane & 16) ? 8 : 0)) * PW * 4 +
                                     ((lane & 8) ? 16 : 0));
    const int fr = lane >> 2;
    const int c2 = (lane & 3) * 2;

    for (int kt = 0; kt < KT; kt++) {
        asm volatile("cp.async.wait_group 2;" ::: "memory");
        __syncthreads();   // single barrier: stage kt ready AND all kt-1 reads done

        // prefetch stage kt+3 into slot (kt+3)&3 == (kt-1)&3, consumed at kt-1
        const int ps = kt + STAGES - 1;
        if (ps < KT) {
            uint32_t so = (uint32_t)((ps & (STAGES - 1)) * STAGE_WORDS * 4);
            int ko = ps * BK;
            #pragma unroll
            for (int rb = 0; rb < 4; rb++) {
                cp_async16(adst + so + rb * 32 * PW * 4, Ag + (size_t)(rb * 32) * lda + ko);
                cp_async16(bdst + so + rb * 32 * PW * 4, Bg + (size_t)(rb * 32) * ldb + ko);
            }
        }
        asm volatile("cp.async.commit_group;" ::: "memory");

        const uint32_t sA = smbase + (uint32_t)((kt & (STAGES - 1)) * STAGE_WORDS * 4);
        const uint32_t sB = sA + TILE_WORDS * 4;

        // hoist ALL fragment loads (both k16 steps), then all 64 HMMA
        uint32_t af[2][4][4], bfr[2][4][4];
        #pragma unroll
        for (int kk = 0; kk < 2; kk++) {
            const uint32_t kb = (uint32_t)(kk * 32);
            #pragma unroll
            for (int i = 0; i < 4; i++)
                ldm_x4(sA + (uint32_t)((wm + i * 16) * PW * 4) + kb + aoff, af[kk][i]);
            #pragma unroll
            for (int jp = 0; jp < 4; jp++)
                ldm_x4(sB + (uint32_t)((wn + jp * 16) * PW * 4) + kb + boff, bfr[kk][jp]);
        }
        #pragma unroll
        for (int kk = 0; kk < 2; kk++)
            #pragma unroll
            for (int i = 0; i < 4; i++)
                #pragma unroll
                for (int j = 0; j < 8; j++)
                    mma_f16(acc[i][j], af[kk][i], &bfr[kk][j >> 1][(j & 1) * 2]);
    }

    // ---- epilogue ----
    const bool dorelu = (mode == 0) && (n0 >= 512);
    const bool dotr   = (mode == 0) && (n0 < 512);
    #pragma unroll
    for (int i = 0; i < 4; i++) {
        const int row0 = m0 + wm + i * 16 + fr;
        const int row1 = row0 + 8;
        const float s0 = (mode == 0) ? rowscale[row0] : 1.f;
        const float s1 = (mode == 0) ? rowscale[row1] : 1.f;
        #pragma unroll
        for (int j = 0; j < 8; j++) {
            const int col = n0 + wn + j * 8 + c2;
            float v0 = acc[i][j][0] * s0, v1 = acc[i][j][1] * s0;
            float v2 = acc[i][j][2] * s1, v3 = acc[i][j][3] * s1;
            if (dorelu) {
                v0 = fmaxf(v0, 0.f); v1 = fmaxf(v1, 0.f);
                v2 = fmaxf(v2, 0.f); v3 = fmaxf(v3, 0.f);
            }
            *(float2*)&Crm[(size_t)row0 * ldc + col] = make_float2(v0, v1);
            *(float2*)&Crm[(size_t)row1 * ldc + col] = make_float2(v2, v3);
            if (dotr) {
                Ct[(size_t)col * NN + row0] = __float2half_rn(v0);
                Ct[(size_t)(col + 1) * NN + row0] = __float2half_rn(v1);
                Ct[(size_t)col * NN + row1] = __float2half_rn(v2);
                Ct[(size_t)(col + 1) * NN + row1] = __float2half_rn(v3);
            }
        }
    }
}

// ===========================================================================
// finalize: per-row attention epilogue
// ===========================================================================
__global__ void finalize(const float* __restrict__ C1, const float* __restrict__ C2,
                         const float* __restrict__ rinvg,
                         const float* __restrict__ al, const float* __restrict__ ah,
                         const float* __restrict__ amv,
                         const float* __restrict__ attv, float* __restrict__ out)
{
    int i = blockIdx.x;
    int c = threadIdx.x;
    const float* c1 = C1 + (size_t)i * 768;
    const float* c2 = C2 + (size_t)i * 512;
    float inv = rinvg[i];

    float xl = c1[c], xh = c1[256 + c], om = c1[512 + c];
    float gl = c2[c], gh = c2[256 + c];

    float ol = fmaxf((xl + gl) * inv, 0.f);
    float oh = fmaxf(xh - (xh + gh) * inv, 0.f);

    float v0 = ol * al[c], v1 = oh * ah[c], v2 = om * amv[c];
    #pragma unroll
    for (int off = 16; off; off >>= 1) {
        v0 += __shfl_xor_sync(0xffffffffu, v0, off);
        v1 += __shfl_xor_sync(0xffffffffu, v1, off);
        v2 += __shfl_xor_sync(0xffffffffu, v2, off);
    }
    __shared__ float r0[8], r1[8], r2[8];
    __shared__ float att[3];
    int w = c >> 5, lane = c & 31;
    if (lane == 0) { r0[w] = v0; r1[w] = v1; r2[w] = v2; }
    __syncthreads();
    if (c == 0) {
        float t0 = 0.f, t1 = 0.f, t2 = 0.f;
        #pragma unroll
        for (int k = 0; k < 8; k++) { t0 += r0[k]; t1 += r1[k]; t2 += r2[k]; }
        float s0 = 1.f / (1.f + expf(-t0));
        float s1 = 1.f / (1.f + expf(-t1));
        float s2 = 1.f / (1.f + expf(-t2));
        float l[3];
        #pragma unroll
        for (int j = 0; j < 3; j++)
            l[j] = (s0 * attv[0 * 3 + j] + s1 * attv[1 * 3 + j] + s2 * attv[2 * 3 + j]) * (1.f / 3.f);
        float mx = fmaxf(l[0], fmaxf(l[1], l[2]));
        float e0 = expf(l[0] - mx), e1 = expf(l[1] - mx), e2 = expf(l[2] - mx);
        float esum = e0 + e1 + e2;
        att[0] = e0 / esum; att[1] = e1 / esum; att[2] = e2 / esum;
    }
    __syncthreads();
    out[(size_t)i * 256 + c] = 3.f * (att[0] * ol + att[1] * oh + att[2] * om);
}

// ===========================================================================
extern "C" void kernel_launch(void* const* d_in, const int* in_sizes, int n_in,
                              void* d_out, int out_size)
{
    const float* g     = (const float*)d_in[0];
    const float* feats = (const float*)d_in[1];
    const float* wl    = (const float*)d_in[3];
    const float* wh    = (const float*)d_in[4];
    const float* wm    = (const float*)d_in[5];
    const float* al    = (const float*)d_in[6];
    const float* ah    = (const float*)d_in[7];
    const float* amv   = (const float*)d_in[8];
    const float* attv  = (const float*)d_in[9];
    float* out = (float*)d_out;

    float *C1, *C2, *rx, *rg;
    __half *GH, *FH, *WH, *C1t;
    cudaGetSymbolAddress((void**)&GH, d_gh);
    cudaGetSymbolAddress((void**)&FH, d_featsh);
    cudaGetSymbolAddress((void**)&WH, d_Wh);
    cudaGetSymbolAddress((void**)&C1, d_C1);
    cudaGetSymbolAddress((void**)&C1t, d_C1t);
    cudaGetSymbolAddress((void**)&C2, d_C2);
    cudaGetSymbolAddress((void**)&rx, d_rinv_x);
    cudaGetSymbolAddress((void**)&rg, d_rinv_g);

    cudaFuncSetAttribute(gemm_h, cudaFuncAttributeMaxDynamicSharedMemorySize, GSMEM_BYTES);

    // launch 0: fused rowsum_feats + pack_w
    prep_fused<<<1024 + 1536, 256>>>(feats, rx, FH, wl, wh, wm, WH);
    // launch 1: rowsum_g + fp16 copy of g
    rowsum_g<<<NN, 256>>>(g, rg, GH);
    // launch 2: gemm1: C1 = rinv_x * feats @ Wh^T (+relu mlp, +fp16 C1t)
    gemm_h<<<dim3(6, 64), 128, GSMEM_BYTES>>>(FH, INF_, WH, INF_, INF_, 0,
                                              C1, 768, C1t, rx);
    // launch 3 (profiled slot): gemm2: C2 = gh @ C1t^T
    gemm_h<<<dim3(4, 64), 128, GSMEM_BYTES>>>(GH, NN, C1t, NN, NN, 1,
                                              C2, 512, nullptr, nullptr);
    // launch 4: attention epilogue
    finalize<<<NN, 256>>>(C1, C2, rg, al, ah, amv, attv, out);
}